// round 9
// baseline (speedup 1.0000x reference)
#include <cuda_runtime.h>
#include <math.h>

#define G_    2
#define NP_   332
#define NN_   664
#define NE_   21248
#define EPG_  10624
#define D_    332
#define KH_   6
#define K1_   166
#define K2_   83
#define KCAT_ 2324
#define D3_   128
#define MAXDEG 352
#define GRID  148
#define TPB   256
#define SK1   4
#define KSPL1 592
#define SK2   8
#define KSPL2 304
#define NJ1   (6 * 11 * SK1)   /* 264 */
#define NJ2   (6 * 6 * SK2)    /* 288 */
#define HCHUNK 166

typedef unsigned long long u64;
typedef unsigned int u32;

// ---------------- static device scratch (write-once per replay per buffer) ----------------
__device__ float g_A1[(size_t)NN_ * KCAT_];
__device__ float g_A2[(size_t)NP_ * KCAT_];
__device__ float g_part1[SK1][NN_ * D_];
__device__ float g_part2[SK2][NP_ * D_];
__device__ float g_xt1[NN_ * D_];
__device__ float g_xt2[NP_ * D_];
__device__ float g_conv1[NN_ * D_];
__device__ float g_conv2[NP_ * D_];
__device__ float g_hp[NP_ * D_];
__device__ float g_z[G_ * 1328];
__device__ float g_fc1part[8][G_][D_];
__device__ int   g_perm1[G_ * K1_];
__device__ int   g_newidx[NN_];
__device__ int   g_off[NN_ + 1];
__device__ int   g_off2[NP_];
__device__ int   g_deg2[NP_];
__device__ int   g_el[NE_];
__device__ int   g_el2[NE_];
__device__ u32   g_barGen;
__device__ u32   g_barCnt;

struct GG { u64 As[16][64]; float Bs[16][64]; };          // 12KB per half
union Smem {
    struct { GG gg[2]; } g;                                // 24KB
    struct { int cnt[NN_]; int offs[NN_ + 1]; int ts[256]; } c;
    struct { float w[MAXDEG]; int sn[MAXDEG]; float wself; float inv; } a;
    struct { float sc[NP_]; int pm[K1_]; float ss[K1_]; int cnt[K1_]; int offs[K1_ + 1]; int ts[256]; } p;
    struct { float z0[HCHUNK]; float z1[HCHUNK]; } h1;
    struct { float a1[2][D_]; float a2[2][D3_]; } h2;
};

__device__ __forceinline__ u64 pack2(float v) {
    u32 b = __float_as_uint(v);
    return ((u64)b << 32) | (u64)b;
}
__device__ __forceinline__ void ffma2(u64& d, u64 a, u64 b) {
    asm("fma.rn.f32x2 %0, %1, %2, %0;" : "+l"(d) : "l"(a), "l"(b));
}

// ---- software grid barrier: all GRID blocks are co-resident (grid == #SMs, 1 CTA/SM) ----
__device__ __forceinline__ void gbar() {
    __threadfence();
    __syncthreads();
    if (threadIdx.x == 0) {
        u32 gen = atomicAdd(&g_barGen, 0u);
        if (atomicAdd(&g_barCnt, 1u) == GRID - 1) {
            atomicExch(&g_barCnt, 0u);
            atomicAdd(&g_barGen, 1u);
        } else {
            while (atomicAdd(&g_barGen, 0u) == gen) __nanosleep(64);
        }
    }
    __syncthreads();
}

// ---- stage-1 CSR build (block 0 only) ----
__device__ void csr_build(Smem* sm, const int* __restrict__ dst) {
    int tid = threadIdx.x;
    for (int i = tid; i < NN_; i += TPB) sm->c.cnt[i] = 0;
    __syncthreads();
    for (int e = tid; e < NE_; e += TPB) atomicAdd(&sm->c.cnt[dst[e]], 1);
    __syncthreads();
    int base = tid * 3;
    int l0 = (base < NN_) ? sm->c.cnt[base] : 0;
    int l1 = (base + 1 < NN_) ? sm->c.cnt[base + 1] : 0;
    int l2 = (base + 2 < NN_) ? sm->c.cnt[base + 2] : 0;
    int p0 = l0, p1 = l0 + l1, p2 = p1 + l2;
    sm->c.ts[tid] = p2;
    __syncthreads();
    for (int dd = 1; dd < 256; dd <<= 1) {
        int u = (tid >= dd) ? sm->c.ts[tid - dd] : 0;
        __syncthreads();
        sm->c.ts[tid] += u;
        __syncthreads();
    }
    int excl = tid ? sm->c.ts[tid - 1] : 0;
    if (tid == 0) sm->c.offs[0] = 0;
    if (base < NN_)     sm->c.offs[base + 1] = excl + p0;
    if (base + 1 < NN_) sm->c.offs[base + 2] = excl + p1;
    if (base + 2 < NN_) sm->c.offs[base + 3] = excl + p2;
    __syncthreads();
    for (int i = tid; i <= NN_; i += TPB) g_off[i] = sm->c.offs[i];
    for (int i = tid; i < NN_; i += TPB) sm->c.cnt[i] = 0;
    __syncthreads();
    for (int e = tid; e < NE_; e += TPB) {
        int d = dst[e];
        int p = atomicAdd(&sm->c.cnt[d], 1);
        g_el[sm->c.offs[d] + p] = e;
    }
}

// ---- fused gate-MLP + Kronecker expand (one warp per node) ----
__device__ void gates_expand(const float* __restrict__ pos, const float* __restrict__ W1,
                             const float* __restrict__ X, float* __restrict__ Aout,
                             int n, const int* __restrict__ perm, int gw, int nw) {
    int lane = threadIdx.x & 31;
    for (int r = gw; r < n; r += nw) {
        int row = perm ? perm[r] : r;
        const float* p = pos + (size_t)row * D_;
        float acc[KH_];
#pragma unroll
        for (int k = 0; k < KH_; k++) acc[k] = 0.f;
        for (int i = lane; i < D_; i += 32) {
            float pv = p[i];
#pragma unroll
            for (int k = 0; k < KH_; k++) acc[k] += pv * W1[i * KH_ + k];
        }
#pragma unroll
        for (int k = 0; k < KH_; k++)
#pragma unroll
            for (int o = 16; o; o >>= 1) acc[k] += __shfl_xor_sync(0xffffffffu, acc[k], o);
        float h[7];
#pragma unroll
        for (int k = 0; k < KH_; k++) h[k] = fmaxf(acc[k], 0.f);
        h[6] = 1.f;
        const float4* Xr = (const float4*)(X + (size_t)r * D_);
        float4* Ar = (float4*)(Aout + (size_t)r * KCAT_);
#pragma unroll
        for (int k = 0; k < 7; k++) {
            float hv = h[k];
            for (int q = lane; q < 83; q += 32) {
                float4 xv = Xr[q];
                Ar[k * 83 + q] = make_float4(hv * xv.x, hv * xv.y, hv * xv.z, hv * xv.w);
            }
        }
    }
}

// ---- split-K FFMA2 GEMM phase; block = two independent 128-thread halves ----
__device__ void gemm_phase(Smem* sm, const float* __restrict__ Abase,
                           const float* __restrict__ W2, const float* __restrict__ nb,
                           float* PartBase, int partStride,
                           int M, int mtiles, int KSPLv, int njobs) {
    int tid = threadIdx.x;
    int half = tid >> 7;
    int htid = tid & 127;
    int barid = 1 + half;
    GG* gg = &sm->g.gg[half];
    int ty = htid >> 4, tx = htid & 15;
    for (int j = blockIdx.x * 2 + half; j < njobs; j += GRID * 2) {
        int nx = j % 6;
        int rem = j / 6;
        int my = rem % mtiles;
        int z = rem / mtiles;
        int bn = nx * 64, bm = my * 64;
        int k_begin = z * KSPLv;
        int k_end = min(KCAT_, k_begin + KSPLv);
        int nt = (k_end - k_begin + 15) >> 4;
        u64 acc2[8][2];
#pragma unroll
        for (int i = 0; i < 8; i++) { acc2[i][0] = 0ull; acc2[i][1] = 0ull; }
        for (int t = 0; t < nt; t++) {
            int K0 = k_begin + t * 16;
            float4 ra[2], rb[2];
#pragma unroll
            for (int i = 0; i < 2; i++) {
                int idx = htid * 2 + i;
                int row = idx >> 2, k4 = idx & 3;
                int m = bm + row, k = K0 + k4 * 4;
                float4 v = make_float4(0.f, 0.f, 0.f, 0.f);
                if (m < M && k < k_end) v = *(const float4*)&Abase[(size_t)m * KCAT_ + k];
                ra[i] = v;
            }
#pragma unroll
            for (int i = 0; i < 2; i++) {
                int idx = htid * 2 + i;
                int kl = idx >> 4, j4 = idx & 15;
                int k = K0 + kl, o = bn + j4 * 4;
                float4 v = make_float4(0.f, 0.f, 0.f, 0.f);
                if (k < k_end && o < D_) {
                    const float* Brow = (k < KH_ * D_) ? (W2 + (size_t)k * D_)
                                                       : (nb + (size_t)(k - KH_ * D_) * D_);
                    v = *(const float4*)&Brow[o];
                }
                rb[i] = v;
            }
            asm volatile("bar.sync %0, 128;" :: "r"(barid));
#pragma unroll
            for (int i = 0; i < 2; i++) {
                int idx = htid * 2 + i;
                int row = idx >> 2, k4 = idx & 3;
                gg->As[k4 * 4 + 0][row] = pack2(ra[i].x);
                gg->As[k4 * 4 + 1][row] = pack2(ra[i].y);
                gg->As[k4 * 4 + 2][row] = pack2(ra[i].z);
                gg->As[k4 * 4 + 3][row] = pack2(ra[i].w);
                int kl = idx >> 4, j4 = idx & 15;
                *(float4*)&gg->Bs[kl][j4 * 4] = rb[i];
            }
            asm volatile("bar.sync %0, 128;" :: "r"(barid));
#pragma unroll
            for (int kk = 0; kk < 16; kk++) {
                u64 a2[8];
                const ulonglong2* pa = (const ulonglong2*)&gg->As[kk][ty * 8];
#pragma unroll
                for (int q = 0; q < 4; q++) {
                    ulonglong2 v = pa[q];
                    a2[q * 2] = v.x;
                    a2[q * 2 + 1] = v.y;
                }
                ulonglong2 qb = *(const ulonglong2*)&gg->Bs[kk][tx * 4];
                u64 b01 = qb.x, b23 = qb.y;
#pragma unroll
                for (int i = 0; i < 8; i++) {
                    ffma2(acc2[i][0], a2[i], b01);
                    ffma2(acc2[i][1], a2[i], b23);
                }
            }
        }
        float* Pz = PartBase + (size_t)z * partStride;
#pragma unroll
        for (int i = 0; i < 8; i++) {
            int m = bm + ty * 8 + i;
            int o = bn + tx * 4;
            if (m < M && o < D_) {
                float4 r;
                r.x = __uint_as_float((u32)acc2[i][0]);
                r.y = __uint_as_float((u32)(acc2[i][0] >> 32));
                r.z = __uint_as_float((u32)acc2[i][1]);
                r.w = __uint_as_float((u32)(acc2[i][1] >> 32));
                *(float4*)&Pz[m * D_ + o] = r;
            }
        }
    }
}

// ---- per-dst softmax aggregation ----
__device__ void agg_phase(Smem* sm, const float* __restrict__ attr, const int* __restrict__ src,
                          const float* __restrict__ bias, int n, int stage) {
    const float* xt = stage ? g_xt2 : g_xt1;
    float* conv = stage ? g_conv2 : g_conv1;
    const int* el = stage ? g_el2 : g_el;
    int tid = threadIdx.x;
    for (int d = blockIdx.x; d < n; d += GRID) {
        int s0, cnt;
        if (stage) { s0 = g_off2[d]; cnt = g_deg2[d]; }
        else       { s0 = g_off[d];  cnt = g_off[d + 1] - s0; }
        for (int i = tid; i < cnt; i += TPB) {
            int e = el[s0 + i];
            sm->a.w[i] = attr[e];
            int s = src[e];
            sm->a.sn[i] = stage ? g_newidx[s] : s;
        }
        __syncthreads();
        if (tid < 32) {
            float mx = 1.0f;
            for (int i = tid; i < cnt; i += 32) mx = fmaxf(mx, sm->a.w[i]);
#pragma unroll
            for (int o = 16; o; o >>= 1) mx = fmaxf(mx, __shfl_xor_sync(0xffffffffu, mx, o));
            float s2 = (tid == 0) ? __expf(1.f - mx) : 0.f;
            for (int i = tid; i < cnt; i += 32) {
                float e_ = __expf(sm->a.w[i] - mx);
                sm->a.w[i] = e_;
                s2 += e_;
            }
#pragma unroll
            for (int o = 16; o; o >>= 1) s2 += __shfl_xor_sync(0xffffffffu, s2, o);
            if (tid == 0) {
                float inv = 1.f / s2;
                sm->a.inv = inv;
                sm->a.wself = __expf(1.f - mx) * inv;
            }
        }
        __syncthreads();
        float wself = sm->a.wself, inv = sm->a.inv;
        for (int o = tid; o < D_; o += TPB) {
            float acc = 0.f;
            for (int i = 0; i < cnt; i++) acc += sm->a.w[i] * xt[(size_t)sm->a.sn[i] * D_ + o];
            conv[(size_t)d * D_ + o] = acc * inv + wself * xt[(size_t)d * D_ + o] + bias[o];
        }
        __syncthreads();
    }
}

// ---- pool: score + rank topk + (stage0: CSR2) + gather + readout; one block per graph ----
__device__ void pool_phase(Smem* sm, const float* __restrict__ pw, const int* __restrict__ src,
                           const int* __restrict__ dst, int nper, int k, int stage,
                           int zoff, float inv, int gi) {
    const float* conv = stage ? g_conv2 : g_conv1;
    int tid = threadIdx.x;
    int w = tid >> 5, lane = tid & 31;
    for (int nl = w; nl < nper; nl += 8) {
        int node = gi * nper + nl;
        float nrm = 0.f, dot = 0.f;
        for (int i = lane; i < D_; i += 32) {
            float wv = pw[i];
            nrm += wv * wv;
            dot += conv[(size_t)node * D_ + i] * wv;
        }
#pragma unroll
        for (int o = 16; o; o >>= 1) {
            nrm += __shfl_xor_sync(0xffffffffu, nrm, o);
            dot += __shfl_xor_sync(0xffffffffu, dot, o);
        }
        if (lane == 0) {
            float v = dot * rsqrtf(nrm);
            sm->p.sc[nl] = 1.f / (1.f + __expf(-v));
        }
    }
    __syncthreads();
    for (int nl = tid; nl < nper; nl += TPB) {
        float mine = sm->p.sc[nl];
        int rank = 0;
        for (int j2 = 0; j2 < nper; j2++) {
            float sj = sm->p.sc[j2];
            rank += (sj > mine) || (sj == mine && j2 < nl);
        }
        int node = gi * nper + nl;
        if (stage == 0) g_newidx[node] = (rank < k) ? gi * k + rank : -1;
        if (rank < k) {
            if (stage == 0) g_perm1[gi * k + rank] = node;
            sm->p.pm[rank] = node;
            sm->p.ss[rank] = mine;
        }
    }
    __syncthreads();
    if (stage == 0) {
        for (int i = tid; i < k; i += TPB) sm->p.cnt[i] = 0;
        __syncthreads();
        int e0 = gi * EPG_, e1 = e0 + EPG_;
        for (int e = e0 + tid; e < e1; e += TPB) {
            int ns = g_newidx[src[e]], nd = g_newidx[dst[e]];
            if (ns >= 0 && nd >= 0) atomicAdd(&sm->p.cnt[nd - gi * k], 1);
        }
        __syncthreads();
        sm->p.ts[tid] = (tid < k) ? sm->p.cnt[tid] : 0;
        __syncthreads();
        for (int dd = 1; dd < 256; dd <<= 1) {
            int u = (tid >= dd) ? sm->p.ts[tid - dd] : 0;
            __syncthreads();
            sm->p.ts[tid] += u;
            __syncthreads();
        }
        if (tid < k) sm->p.offs[tid + 1] = sm->p.ts[tid];
        if (tid == 0) sm->p.offs[0] = 0;
        __syncthreads();
        for (int i = tid; i < k; i += TPB) {
            g_off2[gi * k + i] = gi * EPG_ + sm->p.offs[i];
            g_deg2[gi * k + i] = sm->p.cnt[i];
            sm->p.cnt[i] = 0;
        }
        __syncthreads();
        for (int e = e0 + tid; e < e1; e += TPB) {
            int ns = g_newidx[src[e]], nd = g_newidx[dst[e]];
            if (ns >= 0 && nd >= 0) {
                int l = nd - gi * k;
                int p2 = atomicAdd(&sm->p.cnt[l], 1);
                g_el2[gi * EPG_ + sm->p.offs[l] + p2] = e;
            }
        }
        __syncthreads();
    }
    for (int o = tid; o < D_; o += TPB) {
        float mx = -3.4e38f, sum = 0.f;
        for (int j2 = 0; j2 < k; j2++) {
            float v = conv[(size_t)sm->p.pm[j2] * D_ + o] * sm->p.ss[j2];
            if (stage == 0) g_hp[(size_t)(gi * k + j2) * D_ + o] = v;
            mx = fmaxf(mx, v);
            sum += v;
        }
        g_z[gi * 1328 + zoff + o] = mx;
        g_z[gi * 1328 + zoff + D_ + o] = sum * inv;
    }
}

__device__ void head1_phase(Smem* sm, const float* __restrict__ fc1W, int b2) {
    int tid = threadIdx.x;
    int i0 = b2 * HCHUNK;
    for (int i = tid; i < HCHUNK; i += TPB) {
        sm->h1.z0[i] = g_z[i0 + i];
        sm->h1.z1[i] = g_z[1328 + i0 + i];
    }
    __syncthreads();
    for (int o = tid; o < D_; o += TPB) {
        float a0 = 0.f, a1 = 0.f;
        for (int i = 0; i < HCHUNK; i++) {
            float wv = fc1W[(size_t)(i0 + i) * D_ + o];
            a0 += sm->h1.z0[i] * wv;
            a1 += sm->h1.z1[i] * wv;
        }
        g_fc1part[b2][0][o] = a0;
        g_fc1part[b2][1][o] = a1;
    }
}

__device__ void head2_phase(Smem* sm, const float* __restrict__ fc1b,
                            const float* __restrict__ bn1g, const float* __restrict__ bn1b,
                            const float* __restrict__ fc2W, const float* __restrict__ fc2b,
                            const float* __restrict__ bn2g, const float* __restrict__ bn2b,
                            const float* __restrict__ fc3W, const float* __restrict__ fc3b,
                            float* __restrict__ out) {
    int tid = threadIdx.x;
    for (int t = tid; t < 2 * D_; t += TPB) {
        int r = t / D_, o = t - r * D_;
        float v = fc1b[o];
#pragma unroll
        for (int b2 = 0; b2 < 8; b2++) v += g_fc1part[b2][r][o];
        sm->h2.a1[r][o] = v;
    }
    __syncthreads();
    for (int t = tid; t < D_; t += TPB) {
        float v0 = sm->h2.a1[0][t], v1 = sm->h2.a1[1][t];
        float m = (v0 + v1) * 0.5f;
        float d0 = v0 - m, d1 = v1 - m;
        float var = (d0 * d0 + d1 * d1) * 0.5f;
        float is = rsqrtf(var + 1e-5f);
        sm->h2.a1[0][t] = fmaxf(d0 * is * bn1g[t] + bn1b[t], 0.f);
        sm->h2.a1[1][t] = fmaxf(d1 * is * bn1g[t] + bn1b[t], 0.f);
    }
    __syncthreads();
    for (int t = tid; t < 2 * D3_; t += TPB) {
        int r = t / D3_, o = t - r * D3_;
        float acc = fc2b[o];
        for (int i = 0; i < D_; i++) acc += sm->h2.a1[r][i] * fc2W[i * D3_ + o];
        sm->h2.a2[r][o] = acc;
    }
    __syncthreads();
    for (int t = tid; t < D3_; t += TPB) {
        float m = (sm->h2.a2[0][t] + sm->h2.a2[1][t]) * 0.5f;
        float d0 = sm->h2.a2[0][t] - m, d1 = sm->h2.a2[1][t] - m;
        float var = (d0 * d0 + d1 * d1) * 0.5f;
        float is = rsqrtf(var + 1e-5f);
        sm->h2.a2[0][t] = fmaxf(d0 * is * bn2g[t] + bn2b[t], 0.f);
        sm->h2.a2[1][t] = fmaxf(d1 * is * bn2g[t] + bn2b[t], 0.f);
    }
    __syncthreads();
    if (tid < 4) {
        int r = tid >> 1, o = tid & 1;
        float acc = fc3b[o];
        for (int i = 0; i < D3_; i++) acc += sm->h2.a2[r][i] * fc3W[i * 2 + o];
        out[r * 2 + o] = acc;
    }
}

// ---------------- the mega-kernel ----------------
__global__ void __launch_bounds__(TPB, 1) mega(
    const float* __restrict__ x, const int* __restrict__ src, const int* __restrict__ dst,
    const float* __restrict__ eat, const float* __restrict__ pos,
    const float* __restrict__ c1W1, const float* __restrict__ c1W2,
    const float* __restrict__ c1nb, const float* __restrict__ c1b, const float* __restrict__ p1w,
    const float* __restrict__ c2W1, const float* __restrict__ c2W2,
    const float* __restrict__ c2nb, const float* __restrict__ c2b, const float* __restrict__ p2w,
    const float* __restrict__ fc1W, const float* __restrict__ fc1b,
    const float* __restrict__ bn1g, const float* __restrict__ bn1b,
    const float* __restrict__ fc2W, const float* __restrict__ fc2b,
    const float* __restrict__ bn2g, const float* __restrict__ bn2b,
    const float* __restrict__ fc3W, const float* __restrict__ fc3b,
    float* __restrict__ out) {
    __shared__ Smem sm;
    int tid = threadIdx.x;
    int b = blockIdx.x;

    // P0: CSR (block 0) + gates1+expand1 (blocks 1..147)
    if (b == 0) csr_build(&sm, dst);
    else gates_expand(pos, c1W1, x, g_A1, NN_, nullptr, (b - 1) * 8 + (tid >> 5), (GRID - 1) * 8);
    gbar();
    // P1: conv1 GEMM
    gemm_phase(&sm, g_A1, c1W2, c1nb, &g_part1[0][0], NN_ * D_, NN_, 11, KSPL1, NJ1);
    gbar();
    // P2: reduce1
    {
        int n4 = NN_ * (D_ / 4);
        for (int t = b * TPB + tid; t < n4; t += GRID * TPB) {
            float4 s = make_float4(0.f, 0.f, 0.f, 0.f);
#pragma unroll
            for (int z = 0; z < SK1; z++) {
                float4 v = ((const float4*)g_part1[z])[t];
                s.x += v.x; s.y += v.y; s.z += v.z; s.w += v.w;
            }
            ((float4*)g_xt1)[t] = s;
        }
    }
    gbar();
    // P3: agg1
    agg_phase(&sm, eat, src, c1b, NN_, 0);
    gbar();
    // P4: pool1 (blocks 0,1)
    if (b < G_) pool_phase(&sm, p1w, src, dst, NP_, K1_, 0, 0, 1.f / (float)K1_, b);
    gbar();
    // P5: gates2+expand2
    gates_expand(pos, c2W1, g_hp, g_A2, NP_, g_perm1, b * 8 + (tid >> 5), GRID * 8);
    gbar();
    // P6: conv2 GEMM
    gemm_phase(&sm, g_A2, c2W2, c2nb, &g_part2[0][0], NP_ * D_, NP_, 6, KSPL2, NJ2);
    gbar();
    // P7: reduce2
    {
        int n4 = NP_ * (D_ / 4);
        for (int t = b * TPB + tid; t < n4; t += GRID * TPB) {
            float4 s = make_float4(0.f, 0.f, 0.f, 0.f);
#pragma unroll
            for (int z = 0; z < SK2; z++) {
                float4 v = ((const float4*)g_part2[z])[t];
                s.x += v.x; s.y += v.y; s.z += v.z; s.w += v.w;
            }
            ((float4*)g_xt2)[t] = s;
        }
    }
    gbar();
    // P8: agg2
    agg_phase(&sm, eat, src, c2b, NP_, 1);
    gbar();
    // P9: pool2 (blocks 0,1)
    if (b < G_) pool_phase(&sm, p2w, src, dst, K1_, K2_, 1, 2 * D_, 1.f / (float)K2_, b);
    gbar();
    // P10: head fc1 partials (blocks 0..7)
    if (b < 8) head1_phase(&sm, fc1W, b);
    gbar();
    // P11: head tail (block 0)
    if (b == 0) head2_phase(&sm, fc1b, bn1g, bn1b, fc2W, fc2b, bn2g, bn2b, fc3W, fc3b, out);
}

extern "C" void kernel_launch(void* const* d_in, const int* in_sizes, int n_in,
                              void* d_out, int out_size) {
    const float* x    = (const float*)d_in[0];
    const int*   ei   = (const int*)d_in[1];
    const float* eat  = (const float*)d_in[3];
    const float* pos  = (const float*)d_in[4];
    const float* c1W1 = (const float*)d_in[6];
    const float* c1W2 = (const float*)d_in[7];
    const float* c1nb = (const float*)d_in[8];
    const float* c1b  = (const float*)d_in[9];
    const float* p1w  = (const float*)d_in[10];
    const float* c2W1 = (const float*)d_in[11];
    const float* c2W2 = (const float*)d_in[12];
    const float* c2nb = (const float*)d_in[13];
    const float* c2b  = (const float*)d_in[14];
    const float* p2w  = (const float*)d_in[15];
    const float* fc1W = (const float*)d_in[16];
    const float* fc1b = (const float*)d_in[17];
    const float* bn1g = (const float*)d_in[18];
    const float* bn1b = (const float*)d_in[19];
    const float* fc2W = (const float*)d_in[20];
    const float* fc2b = (const float*)d_in[21];
    const float* bn2g = (const float*)d_in[22];
    const float* bn2b = (const float*)d_in[23];
    const float* fc3W = (const float*)d_in[24];
    const float* fc3b = (const float*)d_in[25];
    const int* src = ei;
    const int* dst = ei + NE_;
    float* out = (float*)d_out;

    mega<<<GRID, TPB>>>(x, src, dst, eat, pos,
                        c1W1, c1W2, c1nb, c1b, p1w,
                        c2W1, c2W2, c2nb, c2b, p2w,
                        fc1W, fc1b, bn1g, bn1b,
                        fc2W, fc2b, bn2g, bn2b, fc3W, fc3b, out);
}

// round 10
// speedup vs baseline: 1.3541x; 1.3541x over previous
#include <cuda_runtime.h>
#include <math.h>

#define G_    2
#define NP_   332
#define NN_   664
#define NE_   21248
#define EPG_  10624
#define D_    332
#define KH_   6
#define K1_   166
#define K2_   83
#define KCAT_ 2324
#define D3_   128
#define MAXDEG 352
#define SK    8
#define KSPL  304               /* 8*304=2432 >= 2324, multiple of 16 */
#define HCHUNK 166

typedef unsigned long long u64;
typedef unsigned int u32;

// ---------------- static device scratch ----------------
__device__ float g_A[(size_t)NN_ * KCAT_];
__device__ float g_part[SK][NN_ * D_];
__device__ float g_xt[NN_ * D_];
__device__ float g_conv[NN_ * D_];
__device__ float g_hp[NP_ * D_];
__device__ float g_z[G_ * 1328];
__device__ float g_fc1part[8][G_][D_];
__device__ int   g_perm1[G_ * K1_];
__device__ int   g_newidx[NN_];
__device__ int   g_off[NN_ + 1];
__device__ int   g_off2[NP_];
__device__ int   g_deg2[NP_];
__device__ int   g_el[NE_], g_el2[NE_];

__device__ __forceinline__ u64 dup2(float v) {
    u32 b = __float_as_uint(v);
    return (u64)__double_as_longlong(__hiloint2double((int)b, (int)b));
}
__device__ __forceinline__ void ffma2(u64& d, u64 a, u64 b) {
    asm("fma.rn.f32x2 %0, %1, %2, %0;" : "+l"(d) : "l"(a), "l"(b));
}

// ---------------- stage-1 CSR build ----------------
__global__ void k_csr(const int* __restrict__ dst) {
    __shared__ int cnt[NN_];
    __shared__ int offs[NN_ + 1];
    __shared__ int s[1024];
    int t = threadIdx.x;
    for (int i = t; i < NN_; i += 1024) cnt[i] = 0;
    __syncthreads();
    for (int e = t; e < NE_; e += 1024) atomicAdd(&cnt[dst[e]], 1);
    __syncthreads();
    s[t] = (t < NN_) ? cnt[t] : 0;
    __syncthreads();
    for (int d = 1; d < 1024; d <<= 1) {
        int u = (t >= d) ? s[t - d] : 0;
        __syncthreads();
        s[t] += u;
        __syncthreads();
    }
    if (t < NN_) offs[t + 1] = s[t];
    if (t == 0) offs[0] = 0;
    __syncthreads();
    for (int i = t; i <= NN_; i += 1024) g_off[i] = offs[i];
    for (int i = t; i < NN_; i += 1024) cnt[i] = 0;
    __syncthreads();
    for (int e = t; e < NE_; e += 1024) {
        int d = dst[e];
        int p = atomicAdd(&cnt[d], 1);
        g_el[offs[d] + p] = e;
    }
}

// ---------------- fused gate-MLP + Kronecker expand ----------------
__global__ void k_gates_expand(const float* __restrict__ pos, const float* __restrict__ W1,
                               const float* __restrict__ xin, int usePerm) {
    int r = blockIdx.x;
    __shared__ float h[8];
    __shared__ float xs[D_];
    int tid = threadIdx.x;
    int row = usePerm ? g_perm1[r] : r;
    if (tid < 32) {
        const float* p = pos + (size_t)row * D_;
        float acc[KH_];
#pragma unroll
        for (int k = 0; k < KH_; k++) acc[k] = 0.f;
        for (int i = tid; i < D_; i += 32) {
            float pv = p[i];
#pragma unroll
            for (int k = 0; k < KH_; k++) acc[k] += pv * W1[i * KH_ + k];
        }
#pragma unroll
        for (int k = 0; k < KH_; k++)
#pragma unroll
            for (int o = 16; o; o >>= 1) acc[k] += __shfl_xor_sync(0xffffffffu, acc[k], o);
        if (tid == 0) {
#pragma unroll
            for (int k = 0; k < KH_; k++) h[k] = fmaxf(acc[k], 0.f);
            h[KH_] = 1.f;
        }
    }
    const float* x = usePerm ? (g_hp + (size_t)r * D_) : (xin + (size_t)r * D_);
    for (int i = tid; i < D_ / 4; i += blockDim.x)
        ((float4*)xs)[i] = ((const float4*)x)[i];
    __syncthreads();
    float4* out = (float4*)(g_A + (size_t)r * KCAT_);
    for (int c4 = tid; c4 < KCAT_ / 4; c4 += blockDim.x) {
        int c = c4 * 4;
        int k = c / D_, i = c - k * D_;
        float hv = h[k];
        float4 xv = *(const float4*)&xs[i];
        out[c4] = make_float4(hv * xv.x, hv * xv.y, hv * xv.z, hv * xv.w);
    }
}

// ---------------- split-K GEMM: BM=64 BN=128 BK=16, 128 thr, 8x8/thread, FFMA2 ----------------
__global__ void __launch_bounds__(128) k_gemm(const float* __restrict__ W2,
                                              const float* __restrict__ nb, int M) {
    __shared__ float As[2][16][64];        // 8KB
    __shared__ float Bs[2][16][128];       // 16KB
    int bn = blockIdx.x * 128, bm = blockIdx.y * 64, z = blockIdx.z;
    int k_begin = z * KSPL;
    int k_end = min(KCAT_, k_begin + KSPL);
    int tid = threadIdx.x;
    int ty = tid >> 4, tx = tid & 15;      // ty 0..7 (8 rows each), tx 0..15 (4 col-pairs)
    u64 acc2[8][4];
#pragma unroll
    for (int i = 0; i < 8; i++)
#pragma unroll
        for (int q = 0; q < 4; q++) acc2[i][q] = 0ull;

    int nt = (k_end - k_begin + 15) >> 4;
    float4 ra[2], rb[4];

#define LOAD_TILE(K0)                                                                \
    {                                                                                \
        _Pragma("unroll") for (int i = 0; i < 2; i++) {                              \
            int idx = tid * 2 + i;                                                   \
            int row = idx >> 2, k4 = idx & 3;                                        \
            int m = bm + row, k = (K0) + k4 * 4;                                     \
            float4 v = make_float4(0.f, 0.f, 0.f, 0.f);                              \
            if (m < M && k < k_end) v = *(const float4*)&g_A[(size_t)m * KCAT_ + k]; \
            ra[i] = v;                                                               \
        }                                                                            \
        _Pragma("unroll") for (int i = 0; i < 4; i++) {                              \
            int idx = tid * 4 + i;                                                   \
            int kl = idx >> 5, j4 = idx & 31;                                        \
            int k = (K0) + kl, o = bn + j4 * 4;                                      \
            float4 v = make_float4(0.f, 0.f, 0.f, 0.f);                              \
            if (k < k_end && o < D_) {                                               \
                const float* Brow = (k < KH_ * D_) ? (W2 + (size_t)k * D_)           \
                                                   : (nb + (size_t)(k - KH_ * D_) * D_); \
                v = *(const float4*)&Brow[o];                                        \
            }                                                                        \
            rb[i] = v;                                                               \
        }                                                                            \
    }

#define STORE_TILE(B)                                                                \
    {                                                                                \
        _Pragma("unroll") for (int i = 0; i < 2; i++) {                              \
            int idx = tid * 2 + i;                                                   \
            int row = idx >> 2, k4 = idx & 3;                                        \
            As[B][k4 * 4 + 0][row] = ra[i].x;                                        \
            As[B][k4 * 4 + 1][row] = ra[i].y;                                        \
            As[B][k4 * 4 + 2][row] = ra[i].z;                                        \
            As[B][k4 * 4 + 3][row] = ra[i].w;                                        \
        }                                                                            \
        _Pragma("unroll") for (int i = 0; i < 4; i++) {                              \
            int idx = tid * 4 + i;                                                   \
            int kl = idx >> 5, j4 = idx & 31;                                        \
            *(float4*)&Bs[B][kl][j4 * 4] = rb[i];                                    \
        }                                                                            \
    }

    int buf = 0;
    if (nt > 0) {
        LOAD_TILE(k_begin);
        STORE_TILE(0);
    }
    __syncthreads();
    for (int t = 0; t < nt; t++) {
        if (t + 1 < nt) LOAD_TILE(k_begin + (t + 1) * 16);
#pragma unroll
        for (int kk = 0; kk < 16; kk++) {
            float a[8];
            *(float4*)&a[0] = *(const float4*)&As[buf][kk][ty * 8];
            *(float4*)&a[4] = *(const float4*)&As[buf][kk][ty * 8 + 4];
            u64 ad[8];
#pragma unroll
            for (int i = 0; i < 8; i++) ad[i] = dup2(a[i]);
            u64 bu[4];
#pragma unroll
            for (int q = 0; q < 4; q++)
                bu[q] = *(const u64*)&Bs[buf][kk][2 * tx + 32 * q];
#pragma unroll
            for (int i = 0; i < 8; i++)
#pragma unroll
                for (int q = 0; q < 4; q++) ffma2(acc2[i][q], ad[i], bu[q]);
        }
        if (t + 1 < nt) {
            __syncthreads();
            STORE_TILE(buf ^ 1);
            __syncthreads();
            buf ^= 1;
        }
    }
#pragma unroll
    for (int i = 0; i < 8; i++) {
        int m = bm + ty * 8 + i;
        if (m < M) {
#pragma unroll
            for (int q = 0; q < 4; q++) {
                int col = bn + 2 * tx + 32 * q;
                if (col < D_) {
                    float2 r;
                    r.x = __uint_as_float((u32)acc2[i][q]);
                    r.y = __uint_as_float((u32)(acc2[i][q] >> 32));
                    *(float2*)&g_part[z][m * D_ + col] = r;
                }
            }
        }
    }
#undef LOAD_TILE
#undef STORE_TILE
}

__global__ void k_reduce(int M) {
    int t = blockIdx.x * blockDim.x + threadIdx.x;
    int n4 = M * (D_ / 4);
    if (t < n4) {
        float4 s = make_float4(0.f, 0.f, 0.f, 0.f);
#pragma unroll
        for (int z = 0; z < SK; z++) {
            float4 v = ((const float4*)g_part[z])[t];
            s.x += v.x; s.y += v.y; s.z += v.z; s.w += v.w;
        }
        ((float4*)g_xt)[t] = s;
    }
}

// ---------------- per-dst softmax aggregation ----------------
__global__ void k_agg(const float* __restrict__ attr, const int* __restrict__ src,
                      const float* __restrict__ bias, int n, int stage) {
    int d = blockIdx.x;
    if (d >= n) return;
    int s0, cnt;
    if (stage) { s0 = g_off2[d]; cnt = g_deg2[d]; }
    else       { s0 = g_off[d];  cnt = g_off[d + 1] - s0; }
    __shared__ float w[MAXDEG];
    __shared__ int sn[MAXDEG];
    __shared__ float sh_wself, sh_inv;
    int tid = threadIdx.x;
    const int* el = stage ? g_el2 : g_el;
    for (int i = tid; i < cnt; i += blockDim.x) {
        int e = el[s0 + i];
        w[i] = attr[e];
        int s = src[e];
        sn[i] = stage ? g_newidx[s] : s;
    }
    __syncthreads();
    if (tid < 32) {
        float mx = 1.0f;
        for (int i = tid; i < cnt; i += 32) mx = fmaxf(mx, w[i]);
#pragma unroll
        for (int o = 16; o; o >>= 1) mx = fmaxf(mx, __shfl_xor_sync(0xffffffffu, mx, o));
        float sm = (tid == 0) ? __expf(1.f - mx) : 0.f;
        for (int i = tid; i < cnt; i += 32) {
            float e_ = __expf(w[i] - mx);
            w[i] = e_;
            sm += e_;
        }
#pragma unroll
        for (int o = 16; o; o >>= 1) sm += __shfl_xor_sync(0xffffffffu, sm, o);
        if (tid == 0) {
            float inv = 1.f / sm;
            sh_inv = inv;
            sh_wself = __expf(1.f - mx) * inv;
        }
    }
    __syncthreads();
    float wself = sh_wself, inv = sh_inv;
    for (int o = tid; o < D_; o += blockDim.x) {
        float acc = 0.f;
        for (int i = 0; i < cnt; i++) acc += w[i] * g_xt[(size_t)sn[i] * D_ + o];
        g_conv[(size_t)d * D_ + o] = acc * inv + wself * g_xt[(size_t)d * D_ + o] + bias[o];
    }
}

// ---------------- fused pool ----------------
__global__ void k_pool(const float* __restrict__ pw, const int* __restrict__ src,
                       const int* __restrict__ dst, int nper, int k, int stage,
                       int zoff, float inv) {
    int gi = blockIdx.x;
    __shared__ float sc[NP_];
    __shared__ int pm[K1_];
    __shared__ float ss[K1_];
    __shared__ int cnt[K1_];
    __shared__ int offs[K1_ + 1];
    __shared__ int s[512];
    int tid = threadIdx.x;
    int w = tid >> 5, lane = tid & 31;
    for (int nl = w; nl < nper; nl += 16) {
        int node = gi * nper + nl;
        float nrm = 0.f, dot = 0.f;
        for (int i = lane; i < D_; i += 32) {
            float wv = pw[i];
            nrm += wv * wv;
            dot += g_conv[(size_t)node * D_ + i] * wv;
        }
#pragma unroll
        for (int o = 16; o; o >>= 1) {
            nrm += __shfl_xor_sync(0xffffffffu, nrm, o);
            dot += __shfl_xor_sync(0xffffffffu, dot, o);
        }
        if (lane == 0) {
            float v = dot * rsqrtf(nrm);
            sc[nl] = 1.f / (1.f + __expf(-v));
        }
    }
    __syncthreads();
    if (tid < nper) {
        float mine = sc[tid];
        int rank = 0;
        for (int j = 0; j < nper; j++) {
            float sj = sc[j];
            rank += (sj > mine) || (sj == mine && j < tid);
        }
        int node = gi * nper + tid;
        if (stage == 0) g_newidx[node] = (rank < k) ? gi * k + rank : -1;
        if (rank < k) {
            if (stage == 0) g_perm1[gi * k + rank] = node;
            pm[rank] = node;
            ss[rank] = mine;
        }
    }
    __syncthreads();
    if (stage == 0) {
        for (int i = tid; i < k; i += 512) cnt[i] = 0;
        __syncthreads();
        int e0 = gi * EPG_, e1 = e0 + EPG_;
        for (int e = e0 + tid; e < e1; e += 512) {
            int ns = g_newidx[src[e]], nd = g_newidx[dst[e]];
            if (ns >= 0 && nd >= 0) atomicAdd(&cnt[nd - gi * k], 1);
        }
        __syncthreads();
        s[tid] = (tid < k) ? cnt[tid] : 0;
        __syncthreads();
        for (int d = 1; d < 256; d <<= 1) {
            int u = (tid >= d) ? s[tid - d] : 0;
            __syncthreads();
            s[tid] += u;
            __syncthreads();
        }
        if (tid < k) offs[tid + 1] = s[tid];
        if (tid == 0) offs[0] = 0;
        __syncthreads();
        for (int i = tid; i < k; i += 512) {
            g_off2[gi * k + i] = gi * EPG_ + offs[i];
            g_deg2[gi * k + i] = cnt[i];
            cnt[i] = 0;
        }
        __syncthreads();
        for (int e = e0 + tid; e < e1; e += 512) {
            int ns = g_newidx[src[e]], nd = g_newidx[dst[e]];
            if (ns >= 0 && nd >= 0) {
                int l = nd - gi * k;
                int p = atomicAdd(&cnt[l], 1);
                g_el2[gi * EPG_ + offs[l] + p] = e;
            }
        }
    }
    __syncthreads();
    if (tid < D_) {
        float mx = -3.4e38f, sm = 0.f;
        for (int j = 0; j < k; j++) {
            float v = g_conv[(size_t)pm[j] * D_ + tid] * ss[j];
            if (stage == 0) g_hp[(size_t)(gi * k + j) * D_ + tid] = v;
            mx = fmaxf(mx, v);
            sm += v;
        }
        g_z[gi * 1328 + zoff + tid] = mx;
        g_z[gi * 1328 + zoff + D_ + tid] = sm * inv;
    }
}

__global__ void k_head1(const float* __restrict__ fc1W) {
    int b = blockIdx.x;
    int i0 = b * HCHUNK;
    __shared__ float z0[HCHUNK], z1[HCHUNK];
    int t = threadIdx.x;
    for (int i = t; i < HCHUNK; i += 352) {
        z0[i] = g_z[i0 + i];
        z1[i] = g_z[1328 + i0 + i];
    }
    __syncthreads();
    if (t < D_) {
        float a0 = 0.f, a1 = 0.f;
        for (int i = 0; i < HCHUNK; i++) {
            float wv = fc1W[(size_t)(i0 + i) * D_ + t];
            a0 += z0[i] * wv;
            a1 += z1[i] * wv;
        }
        g_fc1part[b][0][t] = a0;
        g_fc1part[b][1][t] = a1;
    }
}

__global__ void k_head2(const float* __restrict__ fc1b,
                        const float* __restrict__ bn1g, const float* __restrict__ bn1b,
                        const float* __restrict__ fc2W, const float* __restrict__ fc2b,
                        const float* __restrict__ bn2g, const float* __restrict__ bn2b,
                        const float* __restrict__ fc3W, const float* __restrict__ fc3b,
                        float* __restrict__ out) {
    __shared__ float a1[2][D_];
    __shared__ float a2[2][D3_];
    int t = threadIdx.x;
    if (t < 2 * D_) {
        int r = t / D_, o = t - r * D_;
        float v = fc1b[o];
#pragma unroll
        for (int b = 0; b < 8; b++) v += g_fc1part[b][r][o];
        a1[r][o] = v;
    }
    __syncthreads();
    if (t < D_) {
        float v0 = a1[0][t], v1 = a1[1][t];
        float m = (v0 + v1) * 0.5f;
        float d0 = v0 - m, d1 = v1 - m;
        float var = (d0 * d0 + d1 * d1) * 0.5f;
        float is = rsqrtf(var + 1e-5f);
        a1[0][t] = fmaxf(d0 * is * bn1g[t] + bn1b[t], 0.f);
        a1[1][t] = fmaxf(d1 * is * bn1g[t] + bn1b[t], 0.f);
    }
    __syncthreads();
    if (t < 2 * D3_) {
        int r = t / D3_, o = t - r * D3_;
        float acc = fc2b[o];
        for (int i = 0; i < D_; i++) acc += a1[r][i] * fc2W[i * D3_ + o];
        a2[r][o] = acc;
    }
    __syncthreads();
    if (t < D3_) {
        float m = (a2[0][t] + a2[1][t]) * 0.5f;
        float d0 = a2[0][t] - m, d1 = a2[1][t] - m;
        float var = (d0 * d0 + d1 * d1) * 0.5f;
        float is = rsqrtf(var + 1e-5f);
        a2[0][t] = fmaxf(d0 * is * bn2g[t] + bn2b[t], 0.f);
        a2[1][t] = fmaxf(d1 * is * bn2g[t] + bn2b[t], 0.f);
    }
    __syncthreads();
    if (t < 4) {
        int r = t >> 1, o = t & 1;
        float acc = fc3b[o];
        for (int i = 0; i < D3_; i++) acc += a2[r][i] * fc3W[i * 2 + o];
        out[r * 2 + o] = acc;
    }
}

extern "C" void kernel_launch(void* const* d_in, const int* in_sizes, int n_in,
                              void* d_out, int out_size) {
    const float* x    = (const float*)d_in[0];
    const int*   ei   = (const int*)d_in[1];
    const float* eat  = (const float*)d_in[3];
    const float* pos  = (const float*)d_in[4];
    const float* c1W1 = (const float*)d_in[6];
    const float* c1W2 = (const float*)d_in[7];
    const float* c1nb = (const float*)d_in[8];
    const float* c1b  = (const float*)d_in[9];
    const float* p1w  = (const float*)d_in[10];
    const float* c2W1 = (const float*)d_in[11];
    const float* c2W2 = (const float*)d_in[12];
    const float* c2nb = (const float*)d_in[13];
    const float* c2b  = (const float*)d_in[14];
    const float* p2w  = (const float*)d_in[15];
    const float* fc1W = (const float*)d_in[16];
    const float* fc1b = (const float*)d_in[17];
    const float* bn1g = (const float*)d_in[18];
    const float* bn1b = (const float*)d_in[19];
    const float* fc2W = (const float*)d_in[20];
    const float* fc2b = (const float*)d_in[21];
    const float* bn2g = (const float*)d_in[22];
    const float* bn2b = (const float*)d_in[23];
    const float* fc3W = (const float*)d_in[24];
    const float* fc3b = (const float*)d_in[25];
    const int* src = ei;
    const int* dst = ei + NE_;
    float* out = (float*)d_out;

    // stage 1: conv1
    k_csr<<<1, 1024>>>(dst);
    k_gates_expand<<<NN_, 256>>>(pos, c1W1, x, 0);
    k_gemm<<<dim3(3, 11, SK), 128>>>(c1W2, c1nb, NN_);
    k_reduce<<<(NN_ * (D_ / 4) + 255) / 256, 256>>>(NN_);
    k_agg<<<NN_, 256>>>(eat, src, c1b, NN_, 0);

    // pool1
    k_pool<<<G_, 512>>>(p1w, src, dst, NP_, K1_, 0, 0, 1.f / (float)K1_);

    // stage 2: conv2
    k_gates_expand<<<NP_, 256>>>(pos, c2W1, nullptr, 1);
    k_gemm<<<dim3(3, 6, SK), 128>>>(c2W2, c2nb, NP_);
    k_reduce<<<(NP_ * (D_ / 4) + 255) / 256, 256>>>(NP_);
    k_agg<<<NP_, 256>>>(eat, src, c2b, NP_, 1);

    // pool2
    k_pool<<<G_, 512>>>(p2w, src, dst, K1_, K2_, 1, 2 * D_, 1.f / (float)K2_);

    // head
    k_head1<<<8, 352>>>(fc1W);
    k_head2<<<1, 704>>>(fc1b, bn1g, bn1b, fc2W, fc2b, bn2g, bn2b, fc3W, fc3b, out);
}